// round 1
// baseline (speedup 1.0000x reference)
#include <cuda_runtime.h>
#include <float.h>
#include <math.h>

// Problem constants (fixed shapes from reference setup_inputs)
#define D_DIM   2048
#define SK      64       // sqrt_K
#define NEXPERT 4096     // SK*SK
#define TOPK    8
#define NMAX    8192

// Scratch for fused projection S = x @ [W1;W2]^T  -> [N, 128]
__device__ float g_S[NMAX * 2 * SK];

// ---------------------------------------------------------------------------
// packed f32x2 helpers (sm_100+): one instruction = 2 fp32 FMAs, exact fp32
// ---------------------------------------------------------------------------
__device__ __forceinline__ unsigned long long pk2(float lo, float hi) {
    unsigned long long r;
    asm("mov.b64 %0, {%1, %2};" : "=l"(r) : "f"(lo), "f"(hi));
    return r;
}
__device__ __forceinline__ void fma2(unsigned long long& d,
                                     unsigned long long a,
                                     unsigned long long b) {
    asm("fma.rn.f32x2 %0, %1, %2, %0;" : "+l"(d) : "l"(a), "l"(b));
}

// ---------------------------------------------------------------------------
// Kernel A: SGEMM  S[N,128] = x[N,2048] @ concat(W1,W2)[128,2048]^T
// Tile: BM=64 rows x BN=128 cols, BK=16, 256 threads, thread tile 4x8.
// Software prefetch (grid = N/64 = 128 -> single wave; must hide DRAM lat).
// ---------------------------------------------------------------------------
#define BM 64
#define BN 128
#define BK 16

__global__ __launch_bounds__(256, 1) void pkr_gemm(
    const float* __restrict__ x,
    const float* __restrict__ W1,
    const float* __restrict__ W2)
{
    __shared__ float As[BK][BM];   // 4 KB
    __shared__ float Bs[BK][BN];   // 8 KB

    const int tid = threadIdx.x;
    const int tx  = tid & 15;       // col group -> cols tx*8 .. tx*8+7
    const int ty  = tid >> 4;       // row group -> rows ty*4 .. ty*4+3
    const int bm0 = blockIdx.x * BM;

    // A global-load task: row ar (0..63), k offset akc (0,4,8,12)
    const int ar  = tid >> 2;
    const int akc = (tid & 3) * 4;
    const float* xp = x + (long long)(bm0 + ar) * D_DIM + akc;

    // B global-load tasks: task tid -> col c0 in [0,64) from W1,
    //                      task tid+256 -> col c0+64 from W2, same k offset
    const int c0  = tid >> 2;
    const int kc0 = (tid & 3) * 4;
    const float* w0 = W1 + (long long)c0 * D_DIM + kc0;
    const float* w1 = W2 + (long long)c0 * D_DIM + kc0;

    unsigned long long acc[4][4];
    #pragma unroll
    for (int i = 0; i < 4; i++)
        #pragma unroll
        for (int j = 0; j < 4; j++) acc[i][j] = 0ULL;

    // prefetch first chunk
    float4 a_pf  = *(const float4*)(xp);
    float4 b0_pf = *(const float4*)(w0);
    float4 b1_pf = *(const float4*)(w1);

    for (int k0 = 0; k0 < D_DIM; k0 += BK) {
        // commit prefetched chunk to smem (A stored k-major-outer, transposed)
        As[akc + 0][ar] = a_pf.x;
        As[akc + 1][ar] = a_pf.y;
        As[akc + 2][ar] = a_pf.z;
        As[akc + 3][ar] = a_pf.w;
        Bs[kc0 + 0][c0] = b0_pf.x;
        Bs[kc0 + 1][c0] = b0_pf.y;
        Bs[kc0 + 2][c0] = b0_pf.z;
        Bs[kc0 + 3][c0] = b0_pf.w;
        Bs[kc0 + 0][c0 + SK] = b1_pf.x;
        Bs[kc0 + 1][c0 + SK] = b1_pf.y;
        Bs[kc0 + 2][c0 + SK] = b1_pf.z;
        Bs[kc0 + 3][c0 + SK] = b1_pf.w;
        __syncthreads();

        // prefetch next chunk while computing this one
        if (k0 + BK < D_DIM) {
            a_pf  = *(const float4*)(xp + k0 + BK);
            b0_pf = *(const float4*)(w0 + k0 + BK);
            b1_pf = *(const float4*)(w1 + k0 + BK);
        }

        #pragma unroll
        for (int kk = 0; kk < BK; kk++) {
            float4 a  = *(const float4*)&As[kk][ty * 4];
            float4 b0 = *(const float4*)&Bs[kk][tx * 8];
            float4 b1 = *(const float4*)&Bs[kk][tx * 8 + 4];
            unsigned long long a2[4] = {pk2(a.x, a.x), pk2(a.y, a.y),
                                        pk2(a.z, a.z), pk2(a.w, a.w)};
            unsigned long long b2[4] = {pk2(b0.x, b0.y), pk2(b0.z, b0.w),
                                        pk2(b1.x, b1.y), pk2(b1.z, b1.w)};
            #pragma unroll
            for (int i = 0; i < 4; i++)
                #pragma unroll
                for (int j = 0; j < 4; j++)
                    fma2(acc[i][j], a2[i], b2[j]);
        }
        __syncthreads();
    }

    // store accumulators (packed pairs are bit-layout = two adjacent floats)
    #pragma unroll
    for (int i = 0; i < 4; i++) {
        long long row = bm0 + ty * 4 + i;
        unsigned long long* sp =
            (unsigned long long*)&g_S[row * (2 * SK) + tx * 8];
        #pragma unroll
        for (int j = 0; j < 4; j++) sp[j] = acc[i][j];
    }
}

// ---------------------------------------------------------------------------
// Kernel B: per-row scores + top-8 + softmax.  One warp per row.
// scores[row, i*64+j] = s1[i] + s2[j];  jax top_k tie-break = lower index.
// ---------------------------------------------------------------------------
__global__ __launch_bounds__(256, 1) void pkr_topk(
    float* __restrict__ idx_out,
    float* __restrict__ probs_out,
    float* __restrict__ scores_out)
{
    __shared__ float sb[8][2 * SK];
    const int w    = threadIdx.x >> 5;
    const int lane = threadIdx.x & 31;
    const long long row = (long long)blockIdx.x * 8 + w;

    const float* srow = g_S + row * (2 * SK);
    #pragma unroll
    for (int u = 0; u < 4; u++) sb[w][lane + u * 32] = srow[lane + u * 32];
    __syncwarp();

    // lane-local sorted top-8 (descending; stable -> earlier index kept on tie)
    float bv[TOPK];
    int   bi[TOPK];
    #pragma unroll
    for (int r = 0; r < TOPK; r++) { bv[r] = -FLT_MAX; bi[r] = 1 << 30; }

    float* srow_out = scores_out ? scores_out + row * NEXPERT : (float*)0;

    for (int t = 0; t < NEXPERT / 32; t++) {
        int c   = t * 32 + lane;
        float v = sb[w][c >> 6] + sb[w][SK + (c & 63)];
        if (srow_out) srow_out[c] = v;
        if (v > bv[TOPK - 1]) {
            bv[TOPK - 1] = v; bi[TOPK - 1] = c;
            #pragma unroll
            for (int s = TOPK - 1; s > 0; s--) {
                if (bv[s] > bv[s - 1]) {
                    float tv = bv[s]; bv[s] = bv[s - 1]; bv[s - 1] = tv;
                    int   ti = bi[s]; bi[s] = bi[s - 1]; bi[s - 1] = ti;
                }
            }
        }
    }

    // warp merge: 8 rounds of butterfly argmax (tie -> lower index)
    float mv[TOPK];
    int   mi[TOPK];
    #pragma unroll
    for (int r = 0; r < TOPK; r++) {
        float v = bv[0];
        int   i = bi[0];
        #pragma unroll
        for (int off = 16; off; off >>= 1) {
            float ov = __shfl_xor_sync(0xffffffffu, v, off);
            int   oi = __shfl_xor_sync(0xffffffffu, i, off);
            if (ov > v || (ov == v && oi < i)) { v = ov; i = oi; }
        }
        mv[r] = v; mi[r] = i;
        if (bv[0] == v && bi[0] == i) {   // I was the owner -> pop head
            #pragma unroll
            for (int s = 0; s < TOPK - 1; s++) { bv[s] = bv[s + 1]; bi[s] = bi[s + 1]; }
            bv[TOPK - 1] = -FLT_MAX; bi[TOPK - 1] = 1 << 30;
        }
    }

    if (lane == 0) {
        float m = mv[0], sum = 0.f, e[TOPK];
        #pragma unroll
        for (int r = 0; r < TOPK; r++) { e[r] = expf(mv[r] - m); sum += e[r]; }
        float inv = 1.f / sum;
        #pragma unroll
        for (int r = 0; r < TOPK; r++) {
            if (idx_out)   idx_out[row * TOPK + r]   = (float)mi[r];
            if (probs_out) probs_out[row * TOPK + r] = e[r] * inv;
        }
    }
}

// ---------------------------------------------------------------------------
extern "C" void kernel_launch(void* const* d_in, const int* in_sizes, int n_in,
                              void* d_out, int out_size) {
    const float* x  = (const float*)d_in[0];
    const float* W1 = (const float*)d_in[1];
    const float* W2 = (const float*)d_in[2];
    (void)n_in;

    int N = in_sizes[0] / D_DIM;   // 8192
    float* out = (float*)d_out;

    // Output = flatten of (topk_idx, probs, scores) as float32 (assumed).
    // Branch defensively on out_size in case only a subset is checked.
    float* idxp = 0;
    float* probp = 0;
    float* scorep = 0;
    long long full = (long long)N * (2 * TOPK + NEXPERT);
    if ((long long)out_size == full) {
        idxp   = out;
        probp  = out + (long long)N * TOPK;
        scorep = out + (long long)N * 2 * TOPK;
    } else if ((long long)out_size == (long long)N * NEXPERT) {
        scorep = out;
    } else if ((long long)out_size == (long long)N * 2 * TOPK) {
        idxp  = out;
        probp = out + (long long)N * TOPK;
    } else {
        // unknown layout: assume full ordering anyway
        idxp   = out;
        probp  = out + (long long)N * TOPK;
        scorep = out + (long long)N * 2 * TOPK;
    }

    pkr_gemm<<<N / BM, 256>>>(x, W1, W2);
    pkr_topk<<<N / 8, 256>>>(idxp, probp, scorep);
}

// round 2
// speedup vs baseline: 1.2195x; 1.2195x over previous
#include <cuda_runtime.h>
#include <float.h>
#include <math.h>

// Problem constants (fixed shapes from reference setup_inputs)
#define D_DIM   2048
#define SK      64       // sqrt_K
#define NEXPERT 4096     // SK*SK
#define TOPK    8
#define NMAX    8192

typedef unsigned long long ULL;

// Scratch for fused projection S = x @ [W1;W2]^T  -> [N, 128]
__device__ float g_S[NMAX * 2 * SK];

// ---------------------------------------------------------------------------
// packed f32x2 helpers (sm_100+): one instruction = 2 fp32 FMAs, exact fp32
// ---------------------------------------------------------------------------
__device__ __forceinline__ ULL pk2(float lo, float hi) {
    ULL r;
    asm("mov.b64 %0, {%1, %2};" : "=l"(r) : "f"(lo), "f"(hi));
    return r;
}
__device__ __forceinline__ void fma2(ULL& d, ULL a, ULL b) {
    asm("fma.rn.f32x2 %0, %1, %2, %0;" : "+l"(d) : "l"(a), "l"(b));
}

// ---------------------------------------------------------------------------
// Kernel A: SGEMM  S[N,128] = x[N,2048] @ concat(W1,W2)[128,2048]^T
// BM=64 x BN=128, BK=16, 256 threads, double-buffered smem.
// Thread tile: 8 rows x 4 cols.  Warp covers 8 rows x all 128 cols
//   -> B: one conflict-free LDS.128 per lane per kk (lane = col-group)
//   -> A: two broadcast LDS.128 per warp per kk
// ---------------------------------------------------------------------------
#define BM 64
#define BN 128
#define BK 16
#define NIT (D_DIM / BK)

__global__ __launch_bounds__(256) void pkr_gemm(
    const float* __restrict__ x,
    const float* __restrict__ W1,
    const float* __restrict__ W2)
{
    __shared__ float As[2][BK][BM];   // 2 x 4 KB
    __shared__ float Bs[2][BK][BN];   // 2 x 8 KB

    const int tid  = threadIdx.x;
    const int w    = tid >> 5;
    const int lane = tid & 31;
    const int bm0  = blockIdx.x * BM;

    // A loader: row ar (0..63) coalesced along k; k offset akc in {0,4,8,12}
    const int ar  = tid >> 2;
    const int akc = (tid & 3) * 4;
    const float* xp = x + (size_t)(bm0 + ar) * D_DIM + akc;

    // B loader: col bc (0..63), k offset bkc in {0,4,8,12}
    //   lanes within a warp span 32 consecutive cols -> conflict-free STS
    const int bc  = tid & 63;
    const int bkc = (tid >> 6) * 4;
    const float* w1p = W1 + (size_t)bc * D_DIM + bkc;
    const float* w2p = W2 + (size_t)bc * D_DIM + bkc;

    ULL acc[8][2];
    #pragma unroll
    for (int i = 0; i < 8; i++) { acc[i][0] = 0ULL; acc[i][1] = 0ULL; }

    // stage 0 fill
    {
        float4 a  = *(const float4*)xp;
        float4 b1 = *(const float4*)w1p;
        float4 b2 = *(const float4*)w2p;
        As[0][akc + 0][ar] = a.x;  As[0][akc + 1][ar] = a.y;
        As[0][akc + 2][ar] = a.z;  As[0][akc + 3][ar] = a.w;
        Bs[0][bkc + 0][bc] = b1.x; Bs[0][bkc + 1][bc] = b1.y;
        Bs[0][bkc + 2][bc] = b1.z; Bs[0][bkc + 3][bc] = b1.w;
        Bs[0][bkc + 0][bc + SK] = b2.x; Bs[0][bkc + 1][bc + SK] = b2.y;
        Bs[0][bkc + 2][bc + SK] = b2.z; Bs[0][bkc + 3][bc + SK] = b2.w;
    }
    __syncthreads();

    int p = 0;
    float4 a_pf, b1_pf, b2_pf;
    for (int it = 0; it < NIT; ++it) {
        const bool has_next = (it + 1) < NIT;
        if (has_next) {
            const int k0 = (it + 1) * BK;
            a_pf  = *(const float4*)(xp  + k0);
            b1_pf = *(const float4*)(w1p + k0);
            b2_pf = *(const float4*)(w2p + k0);
        }

        #pragma unroll
        for (int kk = 0; kk < BK; kk++) {
            float4 a01 = *(const float4*)&As[p][kk][w * 8];
            float4 a23 = *(const float4*)&As[p][kk][w * 8 + 4];
            ulonglong2 bb = *(const ulonglong2*)&Bs[p][kk][lane * 4];
            float av[8] = {a01.x, a01.y, a01.z, a01.w,
                           a23.x, a23.y, a23.z, a23.w};
            #pragma unroll
            for (int i = 0; i < 8; i++) {
                ULL ad = pk2(av[i], av[i]);
                fma2(acc[i][0], ad, bb.x);
                fma2(acc[i][1], ad, bb.y);
            }
        }

        if (has_next) {
            const int q = p ^ 1;
            As[q][akc + 0][ar] = a_pf.x;  As[q][akc + 1][ar] = a_pf.y;
            As[q][akc + 2][ar] = a_pf.z;  As[q][akc + 3][ar] = a_pf.w;
            Bs[q][bkc + 0][bc] = b1_pf.x; Bs[q][bkc + 1][bc] = b1_pf.y;
            Bs[q][bkc + 2][bc] = b1_pf.z; Bs[q][bkc + 3][bc] = b1_pf.w;
            Bs[q][bkc + 0][bc + SK] = b2_pf.x; Bs[q][bkc + 1][bc + SK] = b2_pf.y;
            Bs[q][bkc + 2][bc + SK] = b2_pf.z; Bs[q][bkc + 3][bc + SK] = b2_pf.w;
            __syncthreads();
            p = q;
        }
    }

    // store: thread rows bm0 + w*8 + i, cols lane*4 .. lane*4+3 (16B aligned)
    #pragma unroll
    for (int i = 0; i < 8; i++) {
        const size_t row = (size_t)(bm0 + w * 8 + i);
        ulonglong2 v; v.x = acc[i][0]; v.y = acc[i][1];
        *(ulonglong2*)&g_S[row * (2 * SK) + lane * 4] = v;
    }
}

// ---------------------------------------------------------------------------
// Kernel B: per-row scores + top-8 + softmax.  One warp per row.
// Each lane owns 4 fixed s2 columns in registers; per iter: 1 broadcast LDS
// (s1), 4 FADD, 1 coalesced STG.128, 4 compares.
// ---------------------------------------------------------------------------
__global__ __launch_bounds__(256) void pkr_topk(
    float* __restrict__ idx_out,
    float* __restrict__ probs_out,
    float* __restrict__ scores_out)
{
    __shared__ float sb[8][2 * SK];
    const int w    = threadIdx.x >> 5;
    const int lane = threadIdx.x & 31;
    const size_t row = (size_t)blockIdx.x * 8 + w;

    // load this row's 128 S values (one float4 per lane)
    *(float4*)&sb[w][lane * 4] =
        *(const float4*)&g_S[row * (2 * SK) + lane * 4];
    __syncwarp();

    // fixed s2 quad for this lane
    const int j = (lane & 15) * 4;
    const float4 s2 = *(const float4*)&sb[w][SK + j];
    const int ihalf = lane >> 4;

    float bv[TOPK];
    int   bi[TOPK];
    #pragma unroll
    for (int r = 0; r < TOPK; r++) { bv[r] = -FLT_MAX; bi[r] = 1 << 30; }

    float* __restrict__ srow_out =
        scores_out ? scores_out + row * NEXPERT : (float*)0;

    #pragma unroll 4
    for (int t = 0; t < 32; t++) {
        const int i = t * 2 + ihalf;
        const float s1 = sb[w][i];
        float v0 = s1 + s2.x, v1 = s1 + s2.y, v2 = s1 + s2.z, v3 = s1 + s2.w;
        if (srow_out) {
            float4 v4; v4.x = v0; v4.y = v1; v4.z = v2; v4.w = v3;
            *(float4*)&srow_out[i * SK + j] = v4;   // warp: 512B contiguous
        }
        const int cbase = i * SK + j;
        float vv[4] = {v0, v1, v2, v3};
        #pragma unroll
        for (int u = 0; u < 4; u++) {
            if (vv[u] > bv[TOPK - 1]) {
                bv[TOPK - 1] = vv[u]; bi[TOPK - 1] = cbase + u;
                #pragma unroll
                for (int s = TOPK - 1; s > 0; s--) {
                    if (bv[s] > bv[s - 1]) {
                        float tv = bv[s]; bv[s] = bv[s - 1]; bv[s - 1] = tv;
                        int   ti = bi[s]; bi[s] = bi[s - 1]; bi[s - 1] = ti;
                    }
                }
            }
        }
    }

    // warp merge: 8 rounds of butterfly argmax (tie -> lower index)
    float mv[TOPK];
    int   mi[TOPK];
    #pragma unroll
    for (int r = 0; r < TOPK; r++) {
        float v = bv[0];
        int   i = bi[0];
        #pragma unroll
        for (int off = 16; off; off >>= 1) {
            float ov = __shfl_xor_sync(0xffffffffu, v, off);
            int   oi = __shfl_xor_sync(0xffffffffu, i, off);
            if (ov > v || (ov == v && oi < i)) { v = ov; i = oi; }
        }
        mv[r] = v; mi[r] = i;
        if (bv[0] == v && bi[0] == i) {   // owner pops head
            #pragma unroll
            for (int s = 0; s < TOPK - 1; s++) { bv[s] = bv[s + 1]; bi[s] = bi[s + 1]; }
            bv[TOPK - 1] = -FLT_MAX; bi[TOPK - 1] = 1 << 30;
        }
    }

    if (lane == 0) {
        float m = mv[0], sum = 0.f, e[TOPK];
        #pragma unroll
        for (int r = 0; r < TOPK; r++) { e[r] = expf(mv[r] - m); sum += e[r]; }
        float inv = 1.f / sum;
        #pragma unroll
        for (int r = 0; r < TOPK; r++) {
            if (idx_out)   idx_out[row * TOPK + r]   = (float)mi[r];
            if (probs_out) probs_out[row * TOPK + r] = e[r] * inv;
        }
    }
}

// ---------------------------------------------------------------------------
extern "C" void kernel_launch(void* const* d_in, const int* in_sizes, int n_in,
                              void* d_out, int out_size) {
    const float* x  = (const float*)d_in[0];
    const float* W1 = (const float*)d_in[1];
    const float* W2 = (const float*)d_in[2];
    (void)n_in;

    int N = in_sizes[0] / D_DIM;   // 8192
    float* out = (float*)d_out;

    float* idxp = 0;
    float* probp = 0;
    float* scorep = 0;
    long long full = (long long)N * (2 * TOPK + NEXPERT);
    if ((long long)out_size == full) {
        idxp   = out;
        probp  = out + (long long)N * TOPK;
        scorep = out + (long long)N * 2 * TOPK;
    } else if ((long long)out_size == (long long)N * NEXPERT) {
        scorep = out;
    } else if ((long long)out_size == (long long)N * 2 * TOPK) {
        idxp  = out;
        probp = out + (long long)N * TOPK;
    } else {
        idxp   = out;
        probp  = out + (long long)N * TOPK;
        scorep = out + (long long)N * 2 * TOPK;
    }

    pkr_gemm<<<N / BM, 256>>>(x, W1, W2);
    pkr_topk<<<N / 8, 256>>>(idxp, probp, scorep);
}